// round 10
// baseline (speedup 1.0000x reference)
#include <cuda_runtime.h>
#include <cstdint>
#include <cfloat>

#define B_  16384
#define TD_ 4096
#define L_  1024
#define K_  8192
#define O_  128

// ---------------- scratch (device globals) -----------------------------------
__device__ float  g_ze[(size_t)B_ * L_];      // 64 MB fp32 z_e
__device__ float  g_zq[(size_t)B_ * L_];      // 64 MB fp32 z_q
__device__ float  g_dt[(size_t)B_ * K_];      // 512 MB exact fp32 distances
__device__ float  g_P[B_];
__device__ float  g_c[K_];
__device__ int    g_idx[B_];
__device__ double g_rowloss[B_];

// packed fp32x2 FMA: two IEEE-rn fp32 FMAs per instruction (sm_100+)
#define FMA_X2(acc, a, b) \
    asm("fma.rn.f32x2 %0, %1, %2, %0;" : "+l"(acc) : "l"(a), "l"(b))
__device__ __forceinline__ void unpack_x2(unsigned long long v, float& lo, float& hi) {
    asm("mov.b64 {%0, %1}, %2;" : "=f"(lo), "=f"(hi) : "l"(v));
}

// monotonic float->uint key (order-preserving; distances are positive here)
__device__ __forceinline__ uint32_t fkey(float f) {
    uint32_t b = __float_as_uint(f);
    return (b & 0x80000000u) ? ~b : (b | 0x80000000u);
}

// ================= packed-f32x2 SGEMM: C = A @ B^T + bias ====================
// 128x128x8 tile, 256 threads, 8x8 micro-tile (4 packed col-pairs per row).
// Per-output accumulation chain is sequential over k — bit-identical to the
// proven scalar-FFMA kernel.
__global__ __launch_bounds__(256) void sgemm_x2_nt_bias(
    const float* __restrict__ A, const float* __restrict__ Bm,
    const float* __restrict__ bias, float* __restrict__ C,
    int M, int N, int Kd)
{
    const int BK = 8;
    __shared__ float As2[BK][256];     // A duplicated: As2[k][2r] = As2[k][2r+1]
    __shared__ float Bs[BK][128];

    int bm = blockIdx.y * 128, bn = blockIdx.x * 128;
    int tid = threadIdx.x;
    int tx = tid & 15, ty = tid >> 4;
    int lrow = tid >> 1, lcol = (tid & 1) * 4;

    const float* Aptr = A  + (size_t)(bm + lrow) * Kd + lcol;
    const float* Bptr = Bm + (size_t)(bn + lrow) * Kd + lcol;

    unsigned long long acc2[8][4];
    #pragma unroll
    for (int i = 0; i < 8; i++)
        #pragma unroll
        for (int t = 0; t < 4; t++) acc2[i][t] = 0ull;

    for (int k0 = 0; k0 < Kd; k0 += BK) {
        float4 av = *(const float4*)(Aptr + k0);
        float4 bv = *(const float4*)(Bptr + k0);
        *(float2*)&As2[lcol + 0][2 * lrow] = make_float2(av.x, av.x);
        *(float2*)&As2[lcol + 1][2 * lrow] = make_float2(av.y, av.y);
        *(float2*)&As2[lcol + 2][2 * lrow] = make_float2(av.z, av.z);
        *(float2*)&As2[lcol + 3][2 * lrow] = make_float2(av.w, av.w);
        Bs[lcol + 0][lrow] = bv.x; Bs[lcol + 1][lrow] = bv.y;
        Bs[lcol + 2][lrow] = bv.z; Bs[lcol + 3][lrow] = bv.w;
        __syncthreads();
        #pragma unroll
        for (int kk = 0; kk < BK; kk++) {
            unsigned long long ad[8], bp[4];
            const ulonglong2* ap = (const ulonglong2*)&As2[kk][ty * 16];
            ulonglong2 a0 = ap[0], a1 = ap[1], a2 = ap[2], a3 = ap[3];
            ad[0] = a0.x; ad[1] = a0.y; ad[2] = a1.x; ad[3] = a1.y;
            ad[4] = a2.x; ad[5] = a2.y; ad[6] = a3.x; ad[7] = a3.y;
            const ulonglong2* bq = (const ulonglong2*)&Bs[kk][tx * 8];
            ulonglong2 b0 = bq[0], b1 = bq[1];
            bp[0] = b0.x; bp[1] = b0.y; bp[2] = b1.x; bp[3] = b1.y;
            #pragma unroll
            for (int i = 0; i < 8; i++)
                #pragma unroll
                for (int t = 0; t < 4; t++)
                    FMA_X2(acc2[i][t], ad[i], bp[t]);
        }
        __syncthreads();
    }

    #pragma unroll
    for (int i = 0; i < 8; i++) {
        int r = bm + ty * 8 + i;
        int c = bn + tx * 8;
        float f[8];
        #pragma unroll
        for (int t = 0; t < 4; t++) unpack_x2(acc2[i][t], f[2 * t], f[2 * t + 1]);
        float4 o0, o1;
        o0.x = f[0] + bias[c + 0]; o0.y = f[1] + bias[c + 1];
        o0.z = f[2] + bias[c + 2]; o0.w = f[3] + bias[c + 3];
        o1.x = f[4] + bias[c + 4]; o1.y = f[5] + bias[c + 5];
        o1.z = f[6] + bias[c + 6]; o1.w = f[7] + bias[c + 7];
        *(float4*)&C[(size_t)r * N + c]     = o0;
        *(float4*)&C[(size_t)r * N + c + 4] = o1;
    }
}

// ================= packed-f32x2 dist GEMM: g_dt = (P - 2*(ze@cb^T)) + c ======
// Exact reference rounding chain per element: t = fl(P - fl(2*dot)); d = fl(t+c)
__global__ __launch_bounds__(256) void dist_x2_kernel(
    const float* __restrict__ cb)
{
    const int BK = 8;
    __shared__ float As2[BK][256];
    __shared__ float Bs[BK][128];

    int bm = blockIdx.y * 128, bn = blockIdx.x * 128;
    int tid = threadIdx.x;
    int tx = tid & 15, ty = tid >> 4;
    int lrow = tid >> 1, lcol = (tid & 1) * 4;

    const float* Aptr = g_ze + (size_t)(bm + lrow) * L_ + lcol;
    const float* Bptr = cb   + (size_t)(bn + lrow) * L_ + lcol;

    unsigned long long acc2[8][4];
    #pragma unroll
    for (int i = 0; i < 8; i++)
        #pragma unroll
        for (int t = 0; t < 4; t++) acc2[i][t] = 0ull;

    for (int k0 = 0; k0 < L_; k0 += BK) {
        float4 av = *(const float4*)(Aptr + k0);
        float4 bv = *(const float4*)(Bptr + k0);
        *(float2*)&As2[lcol + 0][2 * lrow] = make_float2(av.x, av.x);
        *(float2*)&As2[lcol + 1][2 * lrow] = make_float2(av.y, av.y);
        *(float2*)&As2[lcol + 2][2 * lrow] = make_float2(av.z, av.z);
        *(float2*)&As2[lcol + 3][2 * lrow] = make_float2(av.w, av.w);
        Bs[lcol + 0][lrow] = bv.x; Bs[lcol + 1][lrow] = bv.y;
        Bs[lcol + 2][lrow] = bv.z; Bs[lcol + 3][lrow] = bv.w;
        __syncthreads();
        #pragma unroll
        for (int kk = 0; kk < BK; kk++) {
            unsigned long long ad[8], bp[4];
            const ulonglong2* ap = (const ulonglong2*)&As2[kk][ty * 16];
            ulonglong2 a0 = ap[0], a1 = ap[1], a2 = ap[2], a3 = ap[3];
            ad[0] = a0.x; ad[1] = a0.y; ad[2] = a1.x; ad[3] = a1.y;
            ad[4] = a2.x; ad[5] = a2.y; ad[6] = a3.x; ad[7] = a3.y;
            const ulonglong2* bq = (const ulonglong2*)&Bs[kk][tx * 8];
            ulonglong2 b0 = bq[0], b1 = bq[1];
            bp[0] = b0.x; bp[1] = b0.y; bp[2] = b1.x; bp[3] = b1.y;
            #pragma unroll
            for (int i = 0; i < 8; i++)
                #pragma unroll
                for (int t = 0; t < 4; t++)
                    FMA_X2(acc2[i][t], ad[i], bp[t]);
        }
        __syncthreads();
    }

    float cv[8];
    #pragma unroll
    for (int j = 0; j < 8; j++) cv[j] = __ldg(&g_c[bn + tx * 8 + j]);

    #pragma unroll
    for (int i = 0; i < 8; i++) {
        int r = bm + ty * 8 + i;
        float P = __ldg(&g_P[r]);
        float f[8];
        #pragma unroll
        for (int t = 0; t < 4; t++) unpack_x2(acc2[i][t], f[2 * t], f[2 * t + 1]);
        float d[8];
        #pragma unroll
        for (int j = 0; j < 8; j++) {
            float tt = P - 2.0f * f[j];
            d[j] = tt + cv[j];
        }
        *(float4*)&g_dt[(size_t)r * K_ + bn + tx * 8]     = make_float4(d[0], d[1], d[2], d[3]);
        *(float4*)&g_dt[(size_t)r * K_ + bn + tx * 8 + 4] = make_float4(d[4], d[5], d[6], d[7]);
    }
}

// ================= exact argmin scan (first-index tie-break) ==================
__global__ void scan_kernel(float* __restrict__ out_idx_f, int write_idx)
{
    int w = threadIdx.x >> 5, lane = threadIdx.x & 31;
    int row = blockIdx.x * 8 + w;
    const float* d = g_dt + (size_t)row * K_;

    unsigned long long best = ~0ull;
    for (int j0 = 0; j0 < K_; j0 += 128) {
        float4 v = *(const float4*)(d + j0 + lane * 4);
        float dv[4] = { v.x, v.y, v.z, v.w };
        #pragma unroll
        for (int e = 0; e < 4; e++) {
            unsigned long long key = ((unsigned long long)fkey(dv[e]) << 32)
                                   | (unsigned long long)(j0 + lane * 4 + e);
            best = min(best, key);
        }
    }
    #pragma unroll
    for (int o = 16; o > 0; o >>= 1) {
        unsigned long long ob = __shfl_xor_sync(0xffffffffu, best, o);
        best = min(best, ob);
    }
    if (lane == 0) {
        int bi = (int)(best & 0xffffffffu);
        g_idx[row] = bi;
        if (write_idx) out_idx_f[row] = (float)bi;
    }
}

// ================= proven small kernels ======================================
__global__ void rowsumsq_kernel(const float* __restrict__ src, float* __restrict__ dst,
                                int rows, int cols)
{
    int row  = blockIdx.x * (blockDim.x >> 5) + (threadIdx.x >> 5);
    int lane = threadIdx.x & 31;
    if (row >= rows) return;
    const float* r = src + (size_t)row * cols;
    double s = 0.0;
    for (int j = lane; j < cols; j += 32) {
        float v = r[j];
        s += (double)v * (double)v;
    }
    #pragma unroll
    for (int o = 16; o > 0; o >>= 1) s += __shfl_down_sync(0xffffffffu, s, o);
    if (lane == 0) dst[row] = (float)s;
}

__global__ void loss_zq_kernel(const float* __restrict__ cb)
{
    int row = blockIdx.x;
    const float* ze = g_ze + (size_t)row * L_;
    const float* q  = cb   + (size_t)g_idx[row] * L_;
    float* zq = g_zq + (size_t)row * L_;
    double s = 0.0;
    for (int j = threadIdx.x; j < L_; j += blockDim.x) {
        float z = ze[j], qq = q[j];
        float dlt = qq - z;
        s += (double)dlt * (double)dlt;
        zq[j] = z + dlt;
    }
    __shared__ double sh[256];
    sh[threadIdx.x] = s;
    __syncthreads();
    for (int o = 128; o > 0; o >>= 1) {
        if (threadIdx.x < o) sh[threadIdx.x] += sh[threadIdx.x + o];
        __syncthreads();
    }
    if (threadIdx.x == 0) g_rowloss[row] = sh[0];
}

__global__ void loss_reduce_kernel(float* __restrict__ out_loss)
{
    __shared__ double sh[256];
    double s = 0.0;
    for (int r = threadIdx.x; r < B_; r += 256) s += g_rowloss[r];
    sh[threadIdx.x] = s;
    __syncthreads();
    for (int o = 128; o > 0; o >>= 1) {
        if (threadIdx.x < o) sh[threadIdx.x] += sh[threadIdx.x + o];
        __syncthreads();
    }
    if (threadIdx.x == 0) {
        float m = (float)(sh[0] / ((double)B_ * (double)L_));
        out_loss[0] = m + 0.25f * m;
    }
}

__global__ void softmax_kernel(float* __restrict__ logits)
{
    int row = blockIdx.x;
    float* p = logits + (size_t)row * O_;
    float v = p[threadIdx.x];
    __shared__ float shm[4];
    float m = v;
    #pragma unroll
    for (int o = 16; o > 0; o >>= 1) m = fmaxf(m, __shfl_xor_sync(0xffffffffu, m, o));
    if ((threadIdx.x & 31) == 0) shm[threadIdx.x >> 5] = m;
    __syncthreads();
    float mm = fmaxf(fmaxf(shm[0], shm[1]), fmaxf(shm[2], shm[3]));
    __syncthreads();
    float e = expf(v - mm);
    float s = e;
    #pragma unroll
    for (int o = 16; o > 0; o >>= 1) s += __shfl_xor_sync(0xffffffffu, s, o);
    if ((threadIdx.x & 31) == 0) shm[threadIdx.x >> 5] = s;
    __syncthreads();
    float ss = shm[0] + shm[1] + shm[2] + shm[3];
    p[threadIdx.x] = e / ss;
}

// ================= launch =====================================================
extern "C" void kernel_launch(void* const* d_in, const int* in_sizes, int n_in,
                              void* d_out, int out_size)
{
    const float* x     = (const float*)d_in[0];
    const float* W_enc = (const float*)d_in[1];
    const float* b_enc = (const float*)d_in[2];
    const float* cb    = (const float*)d_in[3];
    const float* W_cls = (const float*)d_in[4];
    const float* b_cls = (const float*)d_in[5];
    float* out = (float*)d_out;

    float* out_logits = out;
    float* out_loss   = out + (size_t)B_ * O_;
    float* out_idx    = out + (size_t)B_ * O_ + 1;
    int has_loss = (out_size >= B_ * O_ + 1);
    int has_idx  = (out_size >= B_ * O_ + 1 + B_);

    void *p;
    float *ze, *zq, *Pv, *cv;
    cudaGetSymbolAddress(&p, g_ze); ze = (float*)p;
    cudaGetSymbolAddress(&p, g_zq); zq = (float*)p;
    cudaGetSymbolAddress(&p, g_P);  Pv = (float*)p;
    cudaGetSymbolAddress(&p, g_c);  cv = (float*)p;

    // codebook norms
    rowsumsq_kernel<<<K_ / 8, 256>>>(cb, cv, K_, L_);

    // z_e = x @ W_enc^T + b_enc  (packed f32x2, bit-identical chains)
    {
        dim3 grid(L_ / 128, B_ / 128);
        sgemm_x2_nt_bias<<<grid, 256>>>(x, W_enc, b_enc, ze, B_, L_, TD_);
    }
    rowsumsq_kernel<<<B_ / 8, 256>>>(ze, Pv, B_, L_);

    // exact distances (packed f32x2) -> exact argmin scan
    {
        dim3 grid(K_ / 128, B_ / 128);
        dist_x2_kernel<<<grid, 256>>>(cb);
    }
    scan_kernel<<<B_ / 8, 256>>>(out_idx, has_idx);

    // loss + z_q
    loss_zq_kernel<<<B_, 256>>>(cb);
    if (has_loss) loss_reduce_kernel<<<1, 256>>>(out_loss);

    // classifier + softmax
    {
        dim3 grid(O_ / 128, B_ / 128);
        sgemm_x2_nt_bias<<<grid, 256>>>(zq, W_cls, b_cls, out_logits, B_, O_, L_);
    }
    softmax_kernel<<<B_, 128>>>(out_logits);
}

// round 11
// speedup vs baseline: 1.4524x; 1.4524x over previous
#include <cuda_runtime.h>
#include <cuda_fp16.h>
#include <cstdint>
#include <cfloat>

#define B_  16384
#define TD_ 4096
#define L_  1024
#define K_  8192
#define O_  128
#define LW2 (L_ / 2)          // 512 half2 words per row

#define CAND_MAX 16
#define WIN_DOTP 2.0f         // capture window in scaled-dot units (8192*dot)

// ---------------- scratch (device globals) -----------------------------------
__device__ float    g_ze[(size_t)B_ * L_];      // 64 MB fp32 z_e
__device__ float    g_zq[(size_t)B_ * L_];      // 64 MB fp32 z_q
__device__ float    g_dotf[(size_t)B_ * K_];    // 512 MB scaled approx dots
__device__ __half2  g_zh[(size_t)B_ * LW2];     // 32 MB packed half2 z
__device__ __half2  g_cbh[(size_t)K_ * LW2];    // 16 MB packed half2 codebook*8192
__device__ float    g_P[B_];
__device__ float    g_c[K_];
__device__ uint32_t g_rowmax[B_];               // monotonic float keys
__device__ int      g_idx[B_];
__device__ int      g_cand2[(size_t)B_ * CAND_MAX];
__device__ int      g_ncand[B_];
__device__ double   g_rowloss[B_];

// packed fp32x2 FMA: two IEEE-rn fp32 FMAs per instruction (sm_100+)
#define FMA_X2(acc, a, b) \
    asm("fma.rn.f32x2 %0, %1, %2, %0;" : "+l"(acc) : "l"(a), "l"(b))
__device__ __forceinline__ void unpack_x2(unsigned long long v, float& lo, float& hi) {
    asm("mov.b64 {%0, %1}, %2;" : "=f"(lo), "=f"(hi) : "l"(v));
}
__device__ __forceinline__ unsigned long long dup_x2(float b) {
    unsigned long long r;
    asm("mov.b64 %0, {%1, %1};" : "=l"(r) : "f"(b));
    return r;
}

// monotonic float<->uint key (order-preserving under unsigned compare)
__device__ __forceinline__ uint32_t fkey(float f) {
    uint32_t b = __float_as_uint(f);
    return (b & 0x80000000u) ? ~b : (b | 0x80000000u);
}
__device__ __forceinline__ float finv(uint32_t u) {
    uint32_t b = (u & 0x80000000u) ? (u & 0x7fffffffu) : ~u;
    return __uint_as_float(b);
}

// ================= f32x2 SGEMM (row-pair packed): C = A @ B^T + bias =========
// 128x128x8 tile, 256 threads. A-pairs come straight from smem as b64 (rows
// contiguous); B scalars duplicated into (b,b) via register mov. Per-output
// chain is sequential over k -> bit-identical to the scalar-FFMA kernel.
__global__ __launch_bounds__(256) void sgemm_x2_nt_bias(
    const float* __restrict__ A, const float* __restrict__ Bm,
    const float* __restrict__ bias, float* __restrict__ C,
    int M, int N, int Kd)
{
    const int BK = 8;
    __shared__ float As[BK][128];
    __shared__ float Bs[BK][128];

    int bm = blockIdx.y * 128, bn = blockIdx.x * 128;
    int tid = threadIdx.x;
    int tx = tid & 15, ty = tid >> 4;
    int lrow = tid >> 1, lcol = (tid & 1) * 4;

    const float* Aptr = A  + (size_t)(bm + lrow) * Kd + lcol;
    const float* Bptr = Bm + (size_t)(bn + lrow) * Kd + lcol;

    unsigned long long acc2[4][8];   // [row-pair][col]
    #pragma unroll
    for (int rp = 0; rp < 4; rp++)
        #pragma unroll
        for (int j = 0; j < 8; j++) acc2[rp][j] = 0ull;

    for (int k0 = 0; k0 < Kd; k0 += BK) {
        float4 av = *(const float4*)(Aptr + k0);
        float4 bv = *(const float4*)(Bptr + k0);
        As[lcol + 0][lrow] = av.x; As[lcol + 1][lrow] = av.y;
        As[lcol + 2][lrow] = av.z; As[lcol + 3][lrow] = av.w;
        Bs[lcol + 0][lrow] = bv.x; Bs[lcol + 1][lrow] = bv.y;
        Bs[lcol + 2][lrow] = bv.z; Bs[lcol + 3][lrow] = bv.w;
        __syncthreads();
        #pragma unroll
        for (int kk = 0; kk < BK; kk++) {
            // A row-pairs, direct b64 from smem (rows contiguous)
            ulonglong2 a01 = *(const ulonglong2*)&As[kk][ty * 8];
            ulonglong2 a23 = *(const ulonglong2*)&As[kk][ty * 8 + 4];
            unsigned long long ap[4] = { a01.x, a01.y, a23.x, a23.y };
            // B scalars -> duplicated pairs
            float4 b0 = *(const float4*)&Bs[kk][tx * 8];
            float4 b1 = *(const float4*)&Bs[kk][tx * 8 + 4];
            unsigned long long bd[8];
            bd[0] = dup_x2(b0.x); bd[1] = dup_x2(b0.y);
            bd[2] = dup_x2(b0.z); bd[3] = dup_x2(b0.w);
            bd[4] = dup_x2(b1.x); bd[5] = dup_x2(b1.y);
            bd[6] = dup_x2(b1.z); bd[7] = dup_x2(b1.w);
            #pragma unroll
            for (int rp = 0; rp < 4; rp++)
                #pragma unroll
                for (int j = 0; j < 8; j++)
                    FMA_X2(acc2[rp][j], ap[rp], bd[j]);
        }
        __syncthreads();
    }

    #pragma unroll
    for (int rp = 0; rp < 4; rp++) {
        int r0 = bm + ty * 8 + 2 * rp;
        int c = bn + tx * 8;
        float lo[8], hi[8];
        #pragma unroll
        for (int j = 0; j < 8; j++) unpack_x2(acc2[rp][j], lo[j], hi[j]);
        float4 o;
        o.x = lo[0] + bias[c + 0]; o.y = lo[1] + bias[c + 1];
        o.z = lo[2] + bias[c + 2]; o.w = lo[3] + bias[c + 3];
        *(float4*)&C[(size_t)r0 * N + c] = o;
        o.x = lo[4] + bias[c + 4]; o.y = lo[5] + bias[c + 5];
        o.z = lo[6] + bias[c + 6]; o.w = lo[7] + bias[c + 7];
        *(float4*)&C[(size_t)r0 * N + c + 4] = o;
        o.x = hi[0] + bias[c + 0]; o.y = hi[1] + bias[c + 1];
        o.z = hi[2] + bias[c + 2]; o.w = hi[3] + bias[c + 3];
        *(float4*)&C[(size_t)(r0 + 1) * N + c] = o;
        o.x = hi[4] + bias[c + 4]; o.y = hi[5] + bias[c + 5];
        o.z = hi[6] + bias[c + 6]; o.w = hi[7] + bias[c + 7];
        *(float4*)&C[(size_t)(r0 + 1) * N + c + 4] = o;
    }
}

// ================= half2 conversions (R9 proven) ==============================
__global__ void zhalf_kernel(void)
{
    size_t i = (size_t)blockIdx.x * blockDim.x + threadIdx.x;
    const float2 v = *(const float2*)(g_ze + i * 2);
    g_zh[i] = __floats2half2_rn(v.x, v.y);
}

__global__ void cbhalf_kernel(const float* __restrict__ cb)
{
    size_t i = (size_t)blockIdx.x * blockDim.x + threadIdx.x;
    const float2 v = *(const float2*)(cb + i * 2);
    g_cbh[i] = __floats2half2_rn(v.x * 8192.0f, v.y * 8192.0f);
}

__global__ void init_rowmax_kernel(void)
{
    int i = blockIdx.x * blockDim.x + threadIdx.x;
    g_rowmax[i] = 0u;
}

// ================= half2 HFMA2 dot GEMM (R9 proven, unchanged) ===============
__global__ __launch_bounds__(256) void dist_h2_kernel(void)
{
    const int BK = 8;
    __shared__ __half2   As[BK][128];
    __shared__ __half2   Bs[BK][128];
    __shared__ uint32_t  sv[128][16];

    int bm = blockIdx.y * 128, bn = blockIdx.x * 128;
    int tid = threadIdx.x;
    int tx = tid & 15, ty = tid >> 4;
    int lrow = tid >> 1, lcol = (tid & 1) * 4;

    const __half2* Aptr = g_zh  + (size_t)(bm + lrow) * LW2 + lcol;
    const __half2* Bptr = g_cbh + (size_t)(bn + lrow) * LW2 + lcol;

    __half2 acc[8][8];
    #pragma unroll
    for (int i = 0; i < 8; i++)
        #pragma unroll
        for (int j = 0; j < 8; j++) acc[i][j] = __floats2half2_rn(0.f, 0.f);

    for (int k0 = 0; k0 < LW2; k0 += BK) {
        float4 avf = *(const float4*)(Aptr + k0);
        float4 bvf = *(const float4*)(Bptr + k0);
        const __half2* av = (const __half2*)&avf;
        const __half2* bv = (const __half2*)&bvf;
        As[lcol + 0][lrow] = av[0]; As[lcol + 1][lrow] = av[1];
        As[lcol + 2][lrow] = av[2]; As[lcol + 3][lrow] = av[3];
        Bs[lcol + 0][lrow] = bv[0]; Bs[lcol + 1][lrow] = bv[1];
        Bs[lcol + 2][lrow] = bv[2]; Bs[lcol + 3][lrow] = bv[3];
        __syncthreads();
        #pragma unroll
        for (int kk = 0; kk < BK; kk++) {
            __half2 ar[8], br[8];
            float4 a0f = *(const float4*)&As[kk][ty * 8];
            float4 a1f = *(const float4*)&As[kk][ty * 8 + 4];
            float4 b0f = *(const float4*)&Bs[kk][tx * 8];
            float4 b1f = *(const float4*)&Bs[kk][tx * 8 + 4];
            const __half2* a0 = (const __half2*)&a0f;
            const __half2* a1 = (const __half2*)&a1f;
            const __half2* b0 = (const __half2*)&b0f;
            const __half2* b1 = (const __half2*)&b1f;
            #pragma unroll
            for (int t = 0; t < 4; t++) { ar[t] = a0[t]; ar[t + 4] = a1[t]; }
            #pragma unroll
            for (int t = 0; t < 4; t++) { br[t] = b0[t]; br[t + 4] = b1[t]; }
            #pragma unroll
            for (int i = 0; i < 8; i++)
                #pragma unroll
                for (int j = 0; j < 8; j++)
                    acc[i][j] = __hfma2(ar[i], br[j], acc[i][j]);
        }
        __syncthreads();
    }

    #pragma unroll
    for (int i = 0; i < 8; i++) {
        int r = bm + ty * 8 + i;
        float f[8];
        #pragma unroll
        for (int j = 0; j < 8; j++)
            f[j] = __low2float(acc[i][j]) + __high2float(acc[i][j]);
        #pragma unroll
        for (int j = 0; j < 8; j += 4) {
            float4 o = make_float4(f[j], f[j + 1], f[j + 2], f[j + 3]);
            *(float4*)&g_dotf[(size_t)r * K_ + bn + tx * 8 + j] = o;
        }
        uint32_t rm = fkey(f[0]);
        #pragma unroll
        for (int j = 1; j < 8; j++) rm = max(rm, fkey(f[j]));
        sv[ty * 8 + i][tx] = rm;
    }
    __syncthreads();
    if (tid < 128) {
        uint32_t m = sv[tid][0];
        #pragma unroll
        for (int t = 1; t < 16; t++) m = max(m, sv[tid][t]);
        atomicMax(&g_rowmax[bm + tid], m);
    }
}

// ================= candidate collection (R9 proven) ===========================
__global__ void scan_kernel(void)
{
    int w = threadIdx.x >> 5, lane = threadIdx.x & 31;
    int row = blockIdx.x * 8 + w;
    const float* d = g_dotf + (size_t)row * K_;

    float thr = finv(g_rowmax[row]) - WIN_DOTP;

    int cnt = 0;
    for (int j0 = 0; j0 < K_; j0 += 128) {
        float4 v = *(const float4*)(d + j0 + lane * 4);
        float dv[4] = { v.x, v.y, v.z, v.w };
        #pragma unroll
        for (int e = 0; e < 4; e++) {
            unsigned mask = __ballot_sync(0xffffffffu, dv[e] >= thr);
            if (dv[e] >= thr) {
                int slot = cnt + __popc(mask & ((1u << lane) - 1u));
                if (slot < CAND_MAX)
                    g_cand2[(size_t)row * CAND_MAX + slot] = j0 + lane * 4 + e;
            }
            cnt += __popc(mask);
        }
    }
    if (lane == 0) g_ncand[row] = cnt;
}

// ================= exact refinement (proven sequential-fp32 chain) ===========
__global__ void refine_kernel(const float* __restrict__ cb,
                              float* __restrict__ out_idx_f, int write_idx)
{
    int w = threadIdx.x >> 5, lane = threadIdx.x & 31;
    int row = blockIdx.x * 8 + w;
    const float* ze = g_ze + (size_t)row * L_;
    float P = g_P[row];
    int cnt = g_ncand[row];

    float bd = FLT_MAX; int bi = 0x7FFFFFFF;
    if (cnt <= CAND_MAX) {
        if (lane < cnt) {
            int col = g_cand2[(size_t)row * CAND_MAX + lane];
            const float* e = cb + (size_t)col * L_;
            float s = 0.0f;
            #pragma unroll 4
            for (int k = 0; k < L_; k++) s = fmaf(__ldg(&ze[k]), __ldg(&e[k]), s);
            float t = P - 2.0f * s;
            bd = t + __ldg(&g_c[col]);
            bi = col;
        }
    } else {
        for (int col = lane; col < K_; col += 32) {
            const float* e = cb + (size_t)col * L_;
            float s = 0.0f;
            #pragma unroll 4
            for (int k = 0; k < L_; k++) s = fmaf(__ldg(&ze[k]), __ldg(&e[k]), s);
            float t = P - 2.0f * s;
            float dv = t + __ldg(&g_c[col]);
            if (dv < bd || (dv == bd && col < bi)) { bd = dv; bi = col; }
        }
    }
    #pragma unroll
    for (int o = 16; o > 0; o >>= 1) {
        float od = __shfl_xor_sync(0xffffffffu, bd, o);
        int oi = __shfl_xor_sync(0xffffffffu, bi, o);
        if (od < bd || (od == bd && oi < bi)) { bd = od; bi = oi; }
    }
    if (lane == 0) {
        g_idx[row] = bi;
        if (write_idx) out_idx_f[row] = (float)bi;
    }
}

// ================= proven small kernels ======================================
__global__ void rowsumsq_kernel(const float* __restrict__ src, float* __restrict__ dst,
                                int rows, int cols)
{
    int row  = blockIdx.x * (blockDim.x >> 5) + (threadIdx.x >> 5);
    int lane = threadIdx.x & 31;
    if (row >= rows) return;
    const float* r = src + (size_t)row * cols;
    double s = 0.0;
    for (int j = lane; j < cols; j += 32) {
        float v = r[j];
        s += (double)v * (double)v;
    }
    #pragma unroll
    for (int o = 16; o > 0; o >>= 1) s += __shfl_down_sync(0xffffffffu, s, o);
    if (lane == 0) dst[row] = (float)s;
}

__global__ void loss_zq_kernel(const float* __restrict__ cb)
{
    int row = blockIdx.x;
    const float* ze = g_ze + (size_t)row * L_;
    const float* q  = cb   + (size_t)g_idx[row] * L_;
    float* zq = g_zq + (size_t)row * L_;
    double s = 0.0;
    for (int j = threadIdx.x; j < L_; j += blockDim.x) {
        float z = ze[j], qq = q[j];
        float dlt = qq - z;
        s += (double)dlt * (double)dlt;
        zq[j] = z + dlt;
    }
    __shared__ double sh[256];
    sh[threadIdx.x] = s;
    __syncthreads();
    for (int o = 128; o > 0; o >>= 1) {
        if (threadIdx.x < o) sh[threadIdx.x] += sh[threadIdx.x + o];
        __syncthreads();
    }
    if (threadIdx.x == 0) g_rowloss[row] = sh[0];
}

__global__ void loss_reduce_kernel(float* __restrict__ out_loss)
{
    __shared__ double sh[256];
    double s = 0.0;
    for (int r = threadIdx.x; r < B_; r += 256) s += g_rowloss[r];
    sh[threadIdx.x] = s;
    __syncthreads();
    for (int o = 128; o > 0; o >>= 1) {
        if (threadIdx.x < o) sh[threadIdx.x] += sh[threadIdx.x + o];
        __syncthreads();
    }
    if (threadIdx.x == 0) {
        float m = (float)(sh[0] / ((double)B_ * (double)L_));
        out_loss[0] = m + 0.25f * m;
    }
}

__global__ void softmax_kernel(float* __restrict__ logits)
{
    int row = blockIdx.x;
    float* p = logits + (size_t)row * O_;
    float v = p[threadIdx.x];
    __shared__ float shm[4];
    float m = v;
    #pragma unroll
    for (int o = 16; o > 0; o >>= 1) m = fmaxf(m, __shfl_xor_sync(0xffffffffu, m, o));
    if ((threadIdx.x & 31) == 0) shm[threadIdx.x >> 5] = m;
    __syncthreads();
    float mm = fmaxf(fmaxf(shm[0], shm[1]), fmaxf(shm[2], shm[3]));
    __syncthreads();
    float e = expf(v - mm);
    float s = e;
    #pragma unroll
    for (int o = 16; o > 0; o >>= 1) s += __shfl_xor_sync(0xffffffffu, s, o);
    if ((threadIdx.x & 31) == 0) shm[threadIdx.x >> 5] = s;
    __syncthreads();
    float ss = shm[0] + shm[1] + shm[2] + shm[3];
    p[threadIdx.x] = e / ss;
}

// ================= launch =====================================================
extern "C" void kernel_launch(void* const* d_in, const int* in_sizes, int n_in,
                              void* d_out, int out_size)
{
    const float* x     = (const float*)d_in[0];
    const float* W_enc = (const float*)d_in[1];
    const float* b_enc = (const float*)d_in[2];
    const float* cb    = (const float*)d_in[3];
    const float* W_cls = (const float*)d_in[4];
    const float* b_cls = (const float*)d_in[5];
    float* out = (float*)d_out;

    float* out_logits = out;
    float* out_loss   = out + (size_t)B_ * O_;
    float* out_idx    = out + (size_t)B_ * O_ + 1;
    int has_loss = (out_size >= B_ * O_ + 1);
    int has_idx  = (out_size >= B_ * O_ + 1 + B_);

    void *p;
    float *ze, *zq, *Pv, *cv;
    cudaGetSymbolAddress(&p, g_ze); ze = (float*)p;
    cudaGetSymbolAddress(&p, g_zq); zq = (float*)p;
    cudaGetSymbolAddress(&p, g_P);  Pv = (float*)p;
    cudaGetSymbolAddress(&p, g_c);  cv = (float*)p;

    // prep: codebook norms + scaled half2 codebook
    rowsumsq_kernel<<<K_ / 8, 256>>>(cb, cv, K_, L_);
    cbhalf_kernel<<<(unsigned)((size_t)K_ * LW2 / 256), 256>>>(cb);
    init_rowmax_kernel<<<B_ / 256, 256>>>();

    // z_e = x @ W_enc^T + b_enc  (f32x2 row-pair packed, bit-identical chains)
    {
        dim3 grid(L_ / 128, B_ / 128);
        sgemm_x2_nt_bias<<<grid, 256>>>(x, W_enc, b_enc, ze, B_, L_, TD_);
    }
    rowsumsq_kernel<<<B_ / 8, 256>>>(ze, Pv, B_, L_);
    zhalf_kernel<<<(unsigned)((size_t)B_ * LW2 / 256), 256>>>();

    // half2 HFMA2 dot GEMM + rowmax, then collect + exact refine (R9 proven)
    {
        dim3 grid(K_ / 128, B_ / 128);
        dist_h2_kernel<<<grid, 256>>>();
    }
    scan_kernel<<<B_ / 8, 256>>>();
    refine_kernel<<<B_ / 8, 256>>>(cb, out_idx, has_idx);

    // loss + z_q (proven path)
    loss_zq_kernel<<<B_, 256>>>(cb);
    if (has_loss) loss_reduce_kernel<<<1, 256>>>(out_loss);

    // classifier + softmax (f32x2 GEMM + proven softmax)
    {
        dim3 grid(O_ / 128, B_ / 128);
        sgemm_x2_nt_bias<<<grid, 256>>>(zq, W_cls, b_cls, out_logits, B_, O_, L_);
    }
    softmax_kernel<<<B_, 128>>>(out_logits);
}

// round 12
// speedup vs baseline: 1.5118x; 1.0409x over previous
#include <cuda_runtime.h>
#include <cuda_fp16.h>
#include <cstdint>
#include <cfloat>

#define B_  16384
#define TD_ 4096
#define L_  1024
#define K_  8192
#define O_  128
#define LW2 (L_ / 2)          // 512 half2 words per row

#define CAND_MAX 16
#define WIN_DOTP 2.0f         // capture window in scaled-dot units (8192*dot)

// ---------------- scratch (device globals) -----------------------------------
__device__ float    g_ze[(size_t)B_ * L_];      // 64 MB fp32 z_e
__device__ float    g_zq[(size_t)B_ * L_];      // 64 MB fp32 z_q
__device__ float    g_dotf[(size_t)B_ * K_];    // 512 MB scaled approx dots
__device__ __half2  g_zh[(size_t)B_ * LW2];     // 32 MB packed half2 z
__device__ __half2  g_cbh[(size_t)K_ * LW2];    // 16 MB packed half2 codebook*8192
__device__ float    g_P[B_];
__device__ float    g_c[K_];
__device__ uint32_t g_rowmax[B_];               // monotonic float keys
__device__ int      g_idx[B_];
__device__ int      g_cand2[(size_t)B_ * CAND_MAX];
__device__ int      g_ncand[B_];
__device__ double   g_rowloss[B_];

// packed fp32x2 FMA: two IEEE-rn fp32 FMAs per instruction (sm_100+)
#define FMA_X2(acc, a, b) \
    asm("fma.rn.f32x2 %0, %1, %2, %0;" : "+l"(acc) : "l"(a), "l"(b))
__device__ __forceinline__ void unpack_x2(unsigned long long v, float& lo, float& hi) {
    asm("mov.b64 {%0, %1}, %2;" : "=f"(lo), "=f"(hi) : "l"(v));
}
__device__ __forceinline__ unsigned long long dup_x2(float b) {
    unsigned long long r;
    asm("mov.b64 %0, {%1, %1};" : "=l"(r) : "f"(b));
    return r;
}

// monotonic float<->uint key (order-preserving under unsigned compare)
__device__ __forceinline__ uint32_t fkey(float f) {
    uint32_t b = __float_as_uint(f);
    return (b & 0x80000000u) ? ~b : (b | 0x80000000u);
}
__device__ __forceinline__ float finv(uint32_t u) {
    uint32_t b = (u & 0x80000000u) ? (u & 0x7fffffffu) : ~u;
    return __uint_as_float(b);
}

// ================= f32x2 SGEMM, 2-stage pipelined: C = A @ B^T + bias ========
// 128x128x8 tile, 256 threads, row-pair packed accumulators.
// Double-buffered smem + register prefetch: one __syncthreads per K-chunk,
// next chunk's LDG issued before current chunk's compute.
// Accumulation chain per output is identical to R11 (bit-exact).
__global__ __launch_bounds__(256) void sgemm_x2_nt_bias(
    const float* __restrict__ A, const float* __restrict__ Bm,
    const float* __restrict__ bias, float* __restrict__ C,
    int M, int N, int Kd)
{
    const int BK = 8;
    __shared__ float As[2][BK][128];
    __shared__ float Bs[2][BK][128];

    int bm = blockIdx.y * 128, bn = blockIdx.x * 128;
    int tid = threadIdx.x;
    int tx = tid & 15, ty = tid >> 4;
    int lrow = tid >> 1, lcol = (tid & 1) * 4;

    const float* Aptr = A  + (size_t)(bm + lrow) * Kd + lcol;
    const float* Bptr = Bm + (size_t)(bn + lrow) * Kd + lcol;

    unsigned long long acc2[4][8];   // [row-pair][col]
    #pragma unroll
    for (int rp = 0; rp < 4; rp++)
        #pragma unroll
        for (int j = 0; j < 8; j++) acc2[rp][j] = 0ull;

    const int NC = Kd / BK;

    // prologue: chunk 0 into stage 0
    {
        float4 av = *(const float4*)(Aptr);
        float4 bv = *(const float4*)(Bptr);
        As[0][lcol + 0][lrow] = av.x; As[0][lcol + 1][lrow] = av.y;
        As[0][lcol + 2][lrow] = av.z; As[0][lcol + 3][lrow] = av.w;
        Bs[0][lcol + 0][lrow] = bv.x; Bs[0][lcol + 1][lrow] = bv.y;
        Bs[0][lcol + 2][lrow] = bv.z; Bs[0][lcol + 3][lrow] = bv.w;
    }
    __syncthreads();

    for (int c = 0; c < NC; c++) {
        int st = c & 1;
        float4 an, bn2;
        if (c + 1 < NC) {
            an  = *(const float4*)(Aptr + (c + 1) * BK);
            bn2 = *(const float4*)(Bptr + (c + 1) * BK);
        }
        #pragma unroll
        for (int kk = 0; kk < BK; kk++) {
            ulonglong2 a01 = *(const ulonglong2*)&As[st][kk][ty * 8];
            ulonglong2 a23 = *(const ulonglong2*)&As[st][kk][ty * 8 + 4];
            unsigned long long ap[4] = { a01.x, a01.y, a23.x, a23.y };
            float4 b0 = *(const float4*)&Bs[st][kk][tx * 8];
            float4 b1 = *(const float4*)&Bs[st][kk][tx * 8 + 4];
            unsigned long long bd[8];
            bd[0] = dup_x2(b0.x); bd[1] = dup_x2(b0.y);
            bd[2] = dup_x2(b0.z); bd[3] = dup_x2(b0.w);
            bd[4] = dup_x2(b1.x); bd[5] = dup_x2(b1.y);
            bd[6] = dup_x2(b1.z); bd[7] = dup_x2(b1.w);
            #pragma unroll
            for (int rp = 0; rp < 4; rp++)
                #pragma unroll
                for (int j = 0; j < 8; j++)
                    FMA_X2(acc2[rp][j], ap[rp], bd[j]);
        }
        if (c + 1 < NC) {
            int ns = (c + 1) & 1;
            As[ns][lcol + 0][lrow] = an.x; As[ns][lcol + 1][lrow] = an.y;
            As[ns][lcol + 2][lrow] = an.z; As[ns][lcol + 3][lrow] = an.w;
            Bs[ns][lcol + 0][lrow] = bn2.x; Bs[ns][lcol + 1][lrow] = bn2.y;
            Bs[ns][lcol + 2][lrow] = bn2.z; Bs[ns][lcol + 3][lrow] = bn2.w;
        }
        __syncthreads();
    }

    #pragma unroll
    for (int rp = 0; rp < 4; rp++) {
        int r0 = bm + ty * 8 + 2 * rp;
        int c = bn + tx * 8;
        float lo[8], hi[8];
        #pragma unroll
        for (int j = 0; j < 8; j++) unpack_x2(acc2[rp][j], lo[j], hi[j]);
        float4 o;
        o.x = lo[0] + bias[c + 0]; o.y = lo[1] + bias[c + 1];
        o.z = lo[2] + bias[c + 2]; o.w = lo[3] + bias[c + 3];
        *(float4*)&C[(size_t)r0 * N + c] = o;
        o.x = lo[4] + bias[c + 4]; o.y = lo[5] + bias[c + 5];
        o.z = lo[6] + bias[c + 6]; o.w = lo[7] + bias[c + 7];
        *(float4*)&C[(size_t)r0 * N + c + 4] = o;
        o.x = hi[0] + bias[c + 0]; o.y = hi[1] + bias[c + 1];
        o.z = hi[2] + bias[c + 2]; o.w = hi[3] + bias[c + 3];
        *(float4*)&C[(size_t)(r0 + 1) * N + c] = o;
        o.x = hi[4] + bias[c + 4]; o.y = hi[5] + bias[c + 5];
        o.z = hi[6] + bias[c + 6]; o.w = hi[7] + bias[c + 7];
        *(float4*)&C[(size_t)(r0 + 1) * N + c + 4] = o;
    }
}

// ================= half2 conversions (proven) =================================
__global__ void zhalf_kernel(void)
{
    size_t i = (size_t)blockIdx.x * blockDim.x + threadIdx.x;
    const float2 v = *(const float2*)(g_ze + i * 2);
    g_zh[i] = __floats2half2_rn(v.x, v.y);
}

__global__ void cbhalf_kernel(const float* __restrict__ cb)
{
    size_t i = (size_t)blockIdx.x * blockDim.x + threadIdx.x;
    const float2 v = *(const float2*)(cb + i * 2);
    g_cbh[i] = __floats2half2_rn(v.x * 8192.0f, v.y * 8192.0f);
}

__global__ void init_rowmax_kernel(void)
{
    int i = blockIdx.x * blockDim.x + threadIdx.x;
    g_rowmax[i] = 0u;
}

// ================= half2 HFMA2 dot GEMM, 2-stage pipelined ===================
__global__ __launch_bounds__(256) void dist_h2_kernel(void)
{
    const int BK = 8;
    __shared__ __half2   As[2][BK][128];
    __shared__ __half2   Bs[2][BK][128];
    __shared__ uint32_t  sv[128][16];

    int bm = blockIdx.y * 128, bn = blockIdx.x * 128;
    int tid = threadIdx.x;
    int tx = tid & 15, ty = tid >> 4;
    int lrow = tid >> 1, lcol = (tid & 1) * 4;

    const __half2* Aptr = g_zh  + (size_t)(bm + lrow) * LW2 + lcol;
    const __half2* Bptr = g_cbh + (size_t)(bn + lrow) * LW2 + lcol;

    __half2 acc[8][8];
    #pragma unroll
    for (int i = 0; i < 8; i++)
        #pragma unroll
        for (int j = 0; j < 8; j++) acc[i][j] = __floats2half2_rn(0.f, 0.f);

    const int NC = LW2 / BK;   // 64

    // prologue: chunk 0 into stage 0
    {
        float4 avf = *(const float4*)(Aptr);
        float4 bvf = *(const float4*)(Bptr);
        const __half2* av = (const __half2*)&avf;
        const __half2* bv = (const __half2*)&bvf;
        As[0][lcol + 0][lrow] = av[0]; As[0][lcol + 1][lrow] = av[1];
        As[0][lcol + 2][lrow] = av[2]; As[0][lcol + 3][lrow] = av[3];
        Bs[0][lcol + 0][lrow] = bv[0]; Bs[0][lcol + 1][lrow] = bv[1];
        Bs[0][lcol + 2][lrow] = bv[2]; Bs[0][lcol + 3][lrow] = bv[3];
    }
    __syncthreads();

    for (int c = 0; c < NC; c++) {
        int st = c & 1;
        float4 anf, bnf;
        if (c + 1 < NC) {
            anf = *(const float4*)(Aptr + (c + 1) * BK);
            bnf = *(const float4*)(Bptr + (c + 1) * BK);
        }
        #pragma unroll
        for (int kk = 0; kk < BK; kk++) {
            __half2 ar[8], br[8];
            float4 a0f = *(const float4*)&As[st][kk][ty * 8];
            float4 a1f = *(const float4*)&As[st][kk][ty * 8 + 4];
            float4 b0f = *(const float4*)&Bs[st][kk][tx * 8];
            float4 b1f = *(const float4*)&Bs[st][kk][tx * 8 + 4];
            const __half2* a0 = (const __half2*)&a0f;
            const __half2* a1 = (const __half2*)&a1f;
            const __half2* b0 = (const __half2*)&b0f;
            const __half2* b1 = (const __half2*)&b1f;
            #pragma unroll
            for (int t = 0; t < 4; t++) { ar[t] = a0[t]; ar[t + 4] = a1[t]; }
            #pragma unroll
            for (int t = 0; t < 4; t++) { br[t] = b0[t]; br[t + 4] = b1[t]; }
            #pragma unroll
            for (int i = 0; i < 8; i++)
                #pragma unroll
                for (int j = 0; j < 8; j++)
                    acc[i][j] = __hfma2(ar[i], br[j], acc[i][j]);
        }
        if (c + 1 < NC) {
            int ns = (c + 1) & 1;
            const __half2* av = (const __half2*)&anf;
            const __half2* bv = (const __half2*)&bnf;
            As[ns][lcol + 0][lrow] = av[0]; As[ns][lcol + 1][lrow] = av[1];
            As[ns][lcol + 2][lrow] = av[2]; As[ns][lcol + 3][lrow] = av[3];
            Bs[ns][lcol + 0][lrow] = bv[0]; Bs[ns][lcol + 1][lrow] = bv[1];
            Bs[ns][lcol + 2][lrow] = bv[2]; Bs[ns][lcol + 3][lrow] = bv[3];
        }
        __syncthreads();
    }

    #pragma unroll
    for (int i = 0; i < 8; i++) {
        int r = bm + ty * 8 + i;
        float f[8];
        #pragma unroll
        for (int j = 0; j < 8; j++)
            f[j] = __low2float(acc[i][j]) + __high2float(acc[i][j]);
        #pragma unroll
        for (int j = 0; j < 8; j += 4) {
            float4 o = make_float4(f[j], f[j + 1], f[j + 2], f[j + 3]);
            *(float4*)&g_dotf[(size_t)r * K_ + bn + tx * 8 + j] = o;
        }
        uint32_t rm = fkey(f[0]);
        #pragma unroll
        for (int j = 1; j < 8; j++) rm = max(rm, fkey(f[j]));
        sv[ty * 8 + i][tx] = rm;
    }
    __syncthreads();
    if (tid < 128) {
        uint32_t m = sv[tid][0];
        #pragma unroll
        for (int t = 1; t < 16; t++) m = max(m, sv[tid][t]);
        atomicMax(&g_rowmax[bm + tid], m);
    }
}

// ================= candidate collection (proven) ==============================
__global__ void scan_kernel(void)
{
    int w = threadIdx.x >> 5, lane = threadIdx.x & 31;
    int row = blockIdx.x * 8 + w;
    const float* d = g_dotf + (size_t)row * K_;

    float thr = finv(g_rowmax[row]) - WIN_DOTP;

    int cnt = 0;
    for (int j0 = 0; j0 < K_; j0 += 128) {
        float4 v = *(const float4*)(d + j0 + lane * 4);
        float dv[4] = { v.x, v.y, v.z, v.w };
        #pragma unroll
        for (int e = 0; e < 4; e++) {
            unsigned mask = __ballot_sync(0xffffffffu, dv[e] >= thr);
            if (dv[e] >= thr) {
                int slot = cnt + __popc(mask & ((1u << lane) - 1u));
                if (slot < CAND_MAX)
                    g_cand2[(size_t)row * CAND_MAX + slot] = j0 + lane * 4 + e;
            }
            cnt += __popc(mask);
        }
    }
    if (lane == 0) g_ncand[row] = cnt;
}

// ================= exact refinement (proven sequential-fp32 chain) ===========
__global__ void refine_kernel(const float* __restrict__ cb,
                              float* __restrict__ out_idx_f, int write_idx)
{
    int w = threadIdx.x >> 5, lane = threadIdx.x & 31;
    int row = blockIdx.x * 8 + w;
    const float* ze = g_ze + (size_t)row * L_;
    float P = g_P[row];
    int cnt = g_ncand[row];

    float bd = FLT_MAX; int bi = 0x7FFFFFFF;
    if (cnt <= CAND_MAX) {
        if (lane < cnt) {
            int col = g_cand2[(size_t)row * CAND_MAX + lane];
            const float* e = cb + (size_t)col * L_;
            float s = 0.0f;
            #pragma unroll 4
            for (int k = 0; k < L_; k++) s = fmaf(__ldg(&ze[k]), __ldg(&e[k]), s);
            float t = P - 2.0f * s;
            bd = t + __ldg(&g_c[col]);
            bi = col;
        }
    } else {
        for (int col = lane; col < K_; col += 32) {
            const float* e = cb + (size_t)col * L_;
            float s = 0.0f;
            #pragma unroll 4
            for (int k = 0; k < L_; k++) s = fmaf(__ldg(&ze[k]), __ldg(&e[k]), s);
            float t = P - 2.0f * s;
            float dv = t + __ldg(&g_c[col]);
            if (dv < bd || (dv == bd && col < bi)) { bd = dv; bi = col; }
        }
    }
    #pragma unroll
    for (int o = 16; o > 0; o >>= 1) {
        float od = __shfl_xor_sync(0xffffffffu, bd, o);
        int oi = __shfl_xor_sync(0xffffffffu, bi, o);
        if (od < bd || (od == bd && oi < bi)) { bd = od; bi = oi; }
    }
    if (lane == 0) {
        g_idx[row] = bi;
        if (write_idx) out_idx_f[row] = (float)bi;
    }
}

// ================= proven small kernels ======================================
__global__ void rowsumsq_kernel(const float* __restrict__ src, float* __restrict__ dst,
                                int rows, int cols)
{
    int row  = blockIdx.x * (blockDim.x >> 5) + (threadIdx.x >> 5);
    int lane = threadIdx.x & 31;
    if (row >= rows) return;
    const float* r = src + (size_t)row * cols;
    double s = 0.0;
    for (int j = lane; j < cols; j += 32) {
        float v = r[j];
        s += (double)v * (double)v;
    }
    #pragma unroll
    for (int o = 16; o > 0; o >>= 1) s += __shfl_down_sync(0xffffffffu, s, o);
    if (lane == 0) dst[row] = (float)s;
}

__global__ void loss_zq_kernel(const float* __restrict__ cb)
{
    int row = blockIdx.x;
    const float* ze = g_ze + (size_t)row * L_;
    const float* q  = cb   + (size_t)g_idx[row] * L_;
    float* zq = g_zq + (size_t)row * L_;
    double s = 0.0;
    for (int j = threadIdx.x; j < L_; j += blockDim.x) {
        float z = ze[j], qq = q[j];
        float dlt = qq - z;
        s += (double)dlt * (double)dlt;
        zq[j] = z + dlt;
    }
    __shared__ double sh[256];
    sh[threadIdx.x] = s;
    __syncthreads();
    for (int o = 128; o > 0; o >>= 1) {
        if (threadIdx.x < o) sh[threadIdx.x] += sh[threadIdx.x + o];
        __syncthreads();
    }
    if (threadIdx.x == 0) g_rowloss[row] = sh[0];
}

__global__ void loss_reduce_kernel(float* __restrict__ out_loss)
{
    __shared__ double sh[256];
    double s = 0.0;
    for (int r = threadIdx.x; r < B_; r += 256) s += g_rowloss[r];
    sh[threadIdx.x] = s;
    __syncthreads();
    for (int o = 128; o > 0; o >>= 1) {
        if (threadIdx.x < o) sh[threadIdx.x] += sh[threadIdx.x + o];
        __syncthreads();
    }
    if (threadIdx.x == 0) {
        float m = (float)(sh[0] / ((double)B_ * (double)L_));
        out_loss[0] = m + 0.25f * m;
    }
}

__global__ void softmax_kernel(float* __restrict__ logits)
{
    int row = blockIdx.x;
    float* p = logits + (size_t)row * O_;
    float v = p[threadIdx.x];
    __shared__ float shm[4];
    float m = v;
    #pragma unroll
    for (int o = 16; o > 0; o >>= 1) m = fmaxf(m, __shfl_xor_sync(0xffffffffu, m, o));
    if ((threadIdx.x & 31) == 0) shm[threadIdx.x >> 5] = m;
    __syncthreads();
    float mm = fmaxf(fmaxf(shm[0], shm[1]), fmaxf(shm[2], shm[3]));
    __syncthreads();
    float e = expf(v - mm);
    float s = e;
    #pragma unroll
    for (int o = 16; o > 0; o >>= 1) s += __shfl_xor_sync(0xffffffffu, s, o);
    if ((threadIdx.x & 31) == 0) shm[threadIdx.x >> 5] = s;
    __syncthreads();
    float ss = shm[0] + shm[1] + shm[2] + shm[3];
    p[threadIdx.x] = e / ss;
}

// ================= launch =====================================================
extern "C" void kernel_launch(void* const* d_in, const int* in_sizes, int n_in,
                              void* d_out, int out_size)
{
    const float* x     = (const float*)d_in[0];
    const float* W_enc = (const float*)d_in[1];
    const float* b_enc = (const float*)d_in[2];
    const float* cb    = (const float*)d_in[3];
    const float* W_cls = (const float*)d_in[4];
    const float* b_cls = (const float*)d_in[5];
    float* out = (float*)d_out;

    float* out_logits = out;
    float* out_loss   = out + (size_t)B_ * O_;
    float* out_idx    = out + (size_t)B_ * O_ + 1;
    int has_loss = (out_size >= B_ * O_ + 1);
    int has_idx  = (out_size >= B_ * O_ + 1 + B_);

    void *p;
    float *ze, *zq, *Pv, *cv;
    cudaGetSymbolAddress(&p, g_ze); ze = (float*)p;
    cudaGetSymbolAddress(&p, g_zq); zq = (float*)p;
    cudaGetSymbolAddress(&p, g_P);  Pv = (float*)p;
    cudaGetSymbolAddress(&p, g_c);  cv = (float*)p;

    // prep: codebook norms + scaled half2 codebook
    rowsumsq_kernel<<<K_ / 8, 256>>>(cb, cv, K_, L_);
    cbhalf_kernel<<<(unsigned)((size_t)K_ * LW2 / 256), 256>>>(cb);
    init_rowmax_kernel<<<B_ / 256, 256>>>();

    // z_e = x @ W_enc^T + b_enc  (f32x2 pipelined, bit-identical chains)
    {
        dim3 grid(L_ / 128, B_ / 128);
        sgemm_x2_nt_bias<<<grid, 256>>>(x, W_enc, b_enc, ze, B_, L_, TD_);
    }
    rowsumsq_kernel<<<B_ / 8, 256>>>(ze, Pv, B_, L_);
    zhalf_kernel<<<(unsigned)((size_t)B_ * LW2 / 256), 256>>>();

    // half2 HFMA2 dot GEMM (pipelined) + rowmax, then collect + exact refine
    {
        dim3 grid(K_ / 128, B_ / 128);
        dist_h2_kernel<<<grid, 256>>>();
    }
    scan_kernel<<<B_ / 8, 256>>>();
    refine_kernel<<<B_ / 8, 256>>>(cb, out_idx, has_idx);

    // loss + z_q (proven path)
    loss_zq_kernel<<<B_, 256>>>(cb);
    if (has_loss) loss_reduce_kernel<<<1, 256>>>(out_loss);

    // classifier + softmax (f32x2 pipelined GEMM + proven softmax)
    {
        dim3 grid(O_ / 128, B_ / 128);
        sgemm_x2_nt_bias<<<grid, 256>>>(zq, W_cls, b_cls, out_logits, B_, O_, L_);
    }
    softmax_kernel<<<B_, 128>>>(out_logits);
}

// round 13
// speedup vs baseline: 1.5925x; 1.0534x over previous
#include <cuda_runtime.h>
#include <cuda_fp16.h>
#include <cstdint>
#include <cfloat>

#define B_  16384
#define TD_ 4096
#define L_  1024
#define K_  8192
#define O_  128
#define LW2 (L_ / 2)          // 512 half2 words per row

#define CAND_MAX 16
#define WIN_DOTP 2.0f         // capture window in scaled-dot units (8192*dot)

// ---------------- scratch (device globals) -----------------------------------
__device__ float    g_ze[(size_t)B_ * L_];      // 64 MB fp32 z_e
__device__ float    g_zq[(size_t)B_ * L_];      // 64 MB fp32 z_q
__device__ float    g_dotf[(size_t)B_ * K_];    // 512 MB scaled approx dots
__device__ __half2  g_zh[(size_t)B_ * LW2];     // 32 MB packed half2 z
__device__ __half2  g_cbh[(size_t)K_ * LW2];    // 16 MB packed half2 codebook*8192
__device__ float    g_P[B_];
__device__ float    g_c[K_];
__device__ uint32_t g_rowmax[B_];               // monotonic float keys
__device__ int      g_idx[B_];
__device__ int      g_cand2[(size_t)B_ * CAND_MAX];
__device__ int      g_ncand[B_];
__device__ double   g_rowloss[B_];

// packed fp32x2 FMA: two IEEE-rn fp32 FMAs per instruction (sm_100+)
#define FMA_X2(acc, a, b) \
    asm("fma.rn.f32x2 %0, %1, %2, %0;" : "+l"(acc) : "l"(a), "l"(b))
__device__ __forceinline__ void unpack_x2(unsigned long long v, float& lo, float& hi) {
    asm("mov.b64 {%0, %1}, %2;" : "=f"(lo), "=f"(hi) : "l"(v));
}
__device__ __forceinline__ unsigned long long dup_x2(float b) {
    unsigned long long r;
    asm("mov.b64 %0, {%1, %1};" : "=l"(r) : "f"(b));
    return r;
}

// monotonic float<->uint key (order-preserving under unsigned compare)
__device__ __forceinline__ uint32_t fkey(float f) {
    uint32_t b = __float_as_uint(f);
    return (b & 0x80000000u) ? ~b : (b | 0x80000000u);
}
__device__ __forceinline__ float finv(uint32_t u) {
    uint32_t b = (u & 0x80000000u) ? (u & 0x7fffffffu) : ~u;
    return __uint_as_float(b);
}

// ================= f32x2 SGEMM, BK=16 pipelined: C = A @ B^T + bias ==========
// 128x128x16 tile, 256 threads, row-pair packed accumulators.
// One __syncthreads per 16-deep K-chunk; chain order identical (bit-exact).
// half_out: also emit half2 of the final values into g_zh (z_e launch only).
__global__ __launch_bounds__(256) void sgemm_x2_nt_bias(
    const float* __restrict__ A, const float* __restrict__ Bm,
    const float* __restrict__ bias, float* __restrict__ C,
    int M, int N, int Kd, int half_out)
{
    const int BK = 16;
    __shared__ float As[2][BK][128];
    __shared__ float Bs[2][BK][128];

    int bm = blockIdx.y * 128, bn = blockIdx.x * 128;
    int tid = threadIdx.x;
    int tx = tid & 15, ty = tid >> 4;
    int lrow = tid >> 1, lk0 = (tid & 1) * 8;

    const float* Aptr = A  + (size_t)(bm + lrow) * Kd + lk0;
    const float* Bptr = Bm + (size_t)(bn + lrow) * Kd + lk0;

    unsigned long long acc2[4][8];   // [row-pair][col]
    #pragma unroll
    for (int rp = 0; rp < 4; rp++)
        #pragma unroll
        for (int j = 0; j < 8; j++) acc2[rp][j] = 0ull;

    const int NC = Kd / BK;

    // prologue: chunk 0 into stage 0
    {
        float4 a0 = *(const float4*)(Aptr);
        float4 a1 = *(const float4*)(Aptr + 4);
        float4 b0 = *(const float4*)(Bptr);
        float4 b1 = *(const float4*)(Bptr + 4);
        As[0][lk0 + 0][lrow] = a0.x; As[0][lk0 + 1][lrow] = a0.y;
        As[0][lk0 + 2][lrow] = a0.z; As[0][lk0 + 3][lrow] = a0.w;
        As[0][lk0 + 4][lrow] = a1.x; As[0][lk0 + 5][lrow] = a1.y;
        As[0][lk0 + 6][lrow] = a1.z; As[0][lk0 + 7][lrow] = a1.w;
        Bs[0][lk0 + 0][lrow] = b0.x; Bs[0][lk0 + 1][lrow] = b0.y;
        Bs[0][lk0 + 2][lrow] = b0.z; Bs[0][lk0 + 3][lrow] = b0.w;
        Bs[0][lk0 + 4][lrow] = b1.x; Bs[0][lk0 + 5][lrow] = b1.y;
        Bs[0][lk0 + 6][lrow] = b1.z; Bs[0][lk0 + 7][lrow] = b1.w;
    }
    __syncthreads();

    for (int c = 0; c < NC; c++) {
        int st = c & 1;
        float4 an0, an1, bn0, bn1;
        if (c + 1 < NC) {
            const float* Ap = Aptr + (c + 1) * BK;
            const float* Bp = Bptr + (c + 1) * BK;
            an0 = *(const float4*)(Ap);     an1 = *(const float4*)(Ap + 4);
            bn0 = *(const float4*)(Bp);     bn1 = *(const float4*)(Bp + 4);
        }
        #pragma unroll
        for (int kk = 0; kk < BK; kk++) {
            ulonglong2 a01 = *(const ulonglong2*)&As[st][kk][ty * 8];
            ulonglong2 a23 = *(const ulonglong2*)&As[st][kk][ty * 8 + 4];
            unsigned long long ap[4] = { a01.x, a01.y, a23.x, a23.y };
            float4 b0 = *(const float4*)&Bs[st][kk][tx * 8];
            float4 b1 = *(const float4*)&Bs[st][kk][tx * 8 + 4];
            unsigned long long bd[8];
            bd[0] = dup_x2(b0.x); bd[1] = dup_x2(b0.y);
            bd[2] = dup_x2(b0.z); bd[3] = dup_x2(b0.w);
            bd[4] = dup_x2(b1.x); bd[5] = dup_x2(b1.y);
            bd[6] = dup_x2(b1.z); bd[7] = dup_x2(b1.w);
            #pragma unroll
            for (int rp = 0; rp < 4; rp++)
                #pragma unroll
                for (int j = 0; j < 8; j++)
                    FMA_X2(acc2[rp][j], ap[rp], bd[j]);
        }
        if (c + 1 < NC) {
            int ns = (c + 1) & 1;
            As[ns][lk0 + 0][lrow] = an0.x; As[ns][lk0 + 1][lrow] = an0.y;
            As[ns][lk0 + 2][lrow] = an0.z; As[ns][lk0 + 3][lrow] = an0.w;
            As[ns][lk0 + 4][lrow] = an1.x; As[ns][lk0 + 5][lrow] = an1.y;
            As[ns][lk0 + 6][lrow] = an1.z; As[ns][lk0 + 7][lrow] = an1.w;
            Bs[ns][lk0 + 0][lrow] = bn0.x; Bs[ns][lk0 + 1][lrow] = bn0.y;
            Bs[ns][lk0 + 2][lrow] = bn0.z; Bs[ns][lk0 + 3][lrow] = bn0.w;
            Bs[ns][lk0 + 4][lrow] = bn1.x; Bs[ns][lk0 + 5][lrow] = bn1.y;
            Bs[ns][lk0 + 6][lrow] = bn1.z; Bs[ns][lk0 + 7][lrow] = bn1.w;
        }
        __syncthreads();
    }

    #pragma unroll
    for (int rp = 0; rp < 4; rp++) {
        int r0 = bm + ty * 8 + 2 * rp;
        int c = bn + tx * 8;
        float lo[8], hi[8];
        #pragma unroll
        for (int j = 0; j < 8; j++) unpack_x2(acc2[rp][j], lo[j], hi[j]);
        #pragma unroll
        for (int j = 0; j < 8; j++) {
            lo[j] += bias[c + j];
            hi[j] += bias[c + j];
        }
        *(float4*)&C[(size_t)r0 * N + c]     = make_float4(lo[0], lo[1], lo[2], lo[3]);
        *(float4*)&C[(size_t)r0 * N + c + 4] = make_float4(lo[4], lo[5], lo[6], lo[7]);
        *(float4*)&C[(size_t)(r0 + 1) * N + c]     = make_float4(hi[0], hi[1], hi[2], hi[3]);
        *(float4*)&C[(size_t)(r0 + 1) * N + c + 4] = make_float4(hi[4], hi[5], hi[6], hi[7]);
        if (half_out) {
            __half2* z0 = g_zh + (size_t)r0 * LW2 + (c >> 1);
            __half2* z1 = g_zh + (size_t)(r0 + 1) * LW2 + (c >> 1);
            #pragma unroll
            for (int t = 0; t < 4; t++) {
                z0[t] = __floats2half2_rn(lo[2 * t], lo[2 * t + 1]);
                z1[t] = __floats2half2_rn(hi[2 * t], hi[2 * t + 1]);
            }
        }
    }
}

// ================= half2 conversions =========================================
__global__ void cbhalf_kernel(const float* __restrict__ cb)
{
    size_t i = (size_t)blockIdx.x * blockDim.x + threadIdx.x;
    const float2 v = *(const float2*)(cb + i * 2);
    g_cbh[i] = __floats2half2_rn(v.x * 8192.0f, v.y * 8192.0f);
}

__global__ void init_rowmax_kernel(void)
{
    int i = blockIdx.x * blockDim.x + threadIdx.x;
    g_rowmax[i] = 0u;
}

// ================= half2 HFMA2 dot GEMM, BK=16 pipelined =====================
__global__ __launch_bounds__(256) void dist_h2_kernel(void)
{
    const int BK = 16;    // 16 half2 words = 32 halves per chunk
    __shared__ __half2   As[2][BK][128];
    __shared__ __half2   Bs[2][BK][128];
    __shared__ uint32_t  sv[128][16];

    int bm = blockIdx.y * 128, bn = blockIdx.x * 128;
    int tid = threadIdx.x;
    int tx = tid & 15, ty = tid >> 4;
    int lrow = tid >> 1, lk0 = (tid & 1) * 8;

    const __half2* Aptr = g_zh  + (size_t)(bm + lrow) * LW2 + lk0;
    const __half2* Bptr = g_cbh + (size_t)(bn + lrow) * LW2 + lk0;

    __half2 acc[8][8];
    #pragma unroll
    for (int i = 0; i < 8; i++)
        #pragma unroll
        for (int j = 0; j < 8; j++) acc[i][j] = __floats2half2_rn(0.f, 0.f);

    const int NC = LW2 / BK;   // 32

    // prologue
    {
        float4 a0f = *(const float4*)(Aptr);
        float4 a1f = *(const float4*)(Aptr + 4);
        float4 b0f = *(const float4*)(Bptr);
        float4 b1f = *(const float4*)(Bptr + 4);
        const __half2* a0 = (const __half2*)&a0f;
        const __half2* a1 = (const __half2*)&a1f;
        const __half2* b0 = (const __half2*)&b0f;
        const __half2* b1 = (const __half2*)&b1f;
        #pragma unroll
        for (int t = 0; t < 4; t++) {
            As[0][lk0 + t][lrow] = a0[t];  As[0][lk0 + 4 + t][lrow] = a1[t];
            Bs[0][lk0 + t][lrow] = b0[t];  Bs[0][lk0 + 4 + t][lrow] = b1[t];
        }
    }
    __syncthreads();

    for (int c = 0; c < NC; c++) {
        int st = c & 1;
        float4 anf0, anf1, bnf0, bnf1;
        if (c + 1 < NC) {
            const __half2* Ap = Aptr + (c + 1) * BK;
            const __half2* Bp = Bptr + (c + 1) * BK;
            anf0 = *(const float4*)(Ap);     anf1 = *(const float4*)(Ap + 4);
            bnf0 = *(const float4*)(Bp);     bnf1 = *(const float4*)(Bp + 4);
        }
        #pragma unroll
        for (int kk = 0; kk < BK; kk++) {
            __half2 ar[8], br[8];
            float4 a0f = *(const float4*)&As[st][kk][ty * 8];
            float4 a1f = *(const float4*)&As[st][kk][ty * 8 + 4];
            float4 b0f = *(const float4*)&Bs[st][kk][tx * 8];
            float4 b1f = *(const float4*)&Bs[st][kk][tx * 8 + 4];
            const __half2* a0 = (const __half2*)&a0f;
            const __half2* a1 = (const __half2*)&a1f;
            const __half2* b0 = (const __half2*)&b0f;
            const __half2* b1 = (const __half2*)&b1f;
            #pragma unroll
            for (int t = 0; t < 4; t++) { ar[t] = a0[t]; ar[t + 4] = a1[t]; }
            #pragma unroll
            for (int t = 0; t < 4; t++) { br[t] = b0[t]; br[t + 4] = b1[t]; }
            #pragma unroll
            for (int i = 0; i < 8; i++)
                #pragma unroll
                for (int j = 0; j < 8; j++)
                    acc[i][j] = __hfma2(ar[i], br[j], acc[i][j]);
        }
        if (c + 1 < NC) {
            int ns = (c + 1) & 1;
            const __half2* a0 = (const __half2*)&anf0;
            const __half2* a1 = (const __half2*)&anf1;
            const __half2* b0 = (const __half2*)&bnf0;
            const __half2* b1 = (const __half2*)&bnf1;
            #pragma unroll
            for (int t = 0; t < 4; t++) {
                As[ns][lk0 + t][lrow] = a0[t];  As[ns][lk0 + 4 + t][lrow] = a1[t];
                Bs[ns][lk0 + t][lrow] = b0[t];  Bs[ns][lk0 + 4 + t][lrow] = b1[t];
            }
        }
        __syncthreads();
    }

    #pragma unroll
    for (int i = 0; i < 8; i++) {
        int r = bm + ty * 8 + i;
        float f[8];
        #pragma unroll
        for (int j = 0; j < 8; j++)
            f[j] = __low2float(acc[i][j]) + __high2float(acc[i][j]);
        #pragma unroll
        for (int j = 0; j < 8; j += 4) {
            float4 o = make_float4(f[j], f[j + 1], f[j + 2], f[j + 3]);
            *(float4*)&g_dotf[(size_t)r * K_ + bn + tx * 8 + j] = o;
        }
        uint32_t rm = fkey(f[0]);
        #pragma unroll
        for (int j = 1; j < 8; j++) rm = max(rm, fkey(f[j]));
        sv[ty * 8 + i][tx] = rm;
    }
    __syncthreads();
    if (tid < 128) {
        uint32_t m = sv[tid][0];
        #pragma unroll
        for (int t = 1; t < 16; t++) m = max(m, sv[tid][t]);
        atomicMax(&g_rowmax[bm + tid], m);
    }
}

// ================= candidate collection (proven) ==============================
__global__ void scan_kernel(void)
{
    int w = threadIdx.x >> 5, lane = threadIdx.x & 31;
    int row = blockIdx.x * 8 + w;
    const float* d = g_dotf + (size_t)row * K_;

    float thr = finv(g_rowmax[row]) - WIN_DOTP;

    int cnt = 0;
    for (int j0 = 0; j0 < K_; j0 += 128) {
        float4 v = *(const float4*)(d + j0 + lane * 4);
        float dv[4] = { v.x, v.y, v.z, v.w };
        #pragma unroll
        for (int e = 0; e < 4; e++) {
            unsigned mask = __ballot_sync(0xffffffffu, dv[e] >= thr);
            if (dv[e] >= thr) {
                int slot = cnt + __popc(mask & ((1u << lane) - 1u));
                if (slot < CAND_MAX)
                    g_cand2[(size_t)row * CAND_MAX + slot] = j0 + lane * 4 + e;
            }
            cnt += __popc(mask);
        }
    }
    if (lane == 0) g_ncand[row] = cnt;
}

// ================= exact refinement (proven sequential-fp32 chain) ===========
__global__ void refine_kernel(const float* __restrict__ cb,
                              float* __restrict__ out_idx_f, int write_idx)
{
    int w = threadIdx.x >> 5, lane = threadIdx.x & 31;
    int row = blockIdx.x * 8 + w;
    const float* ze = g_ze + (size_t)row * L_;
    float P = g_P[row];
    int cnt = g_ncand[row];

    float bd = FLT_MAX; int bi = 0x7FFFFFFF;
    if (cnt <= CAND_MAX) {
        if (lane < cnt) {
            int col = g_cand2[(size_t)row * CAND_MAX + lane];
            const float* e = cb + (size_t)col * L_;
            float s = 0.0f;
            #pragma unroll 4
            for (int k = 0; k < L_; k++) s = fmaf(__ldg(&ze[k]), __ldg(&e[k]), s);
            float t = P - 2.0f * s;
            bd = t + __ldg(&g_c[col]);
            bi = col;
        }
    } else {
        for (int col = lane; col < K_; col += 32) {
            const float* e = cb + (size_t)col * L_;
            float s = 0.0f;
            #pragma unroll 4
            for (int k = 0; k < L_; k++) s = fmaf(__ldg(&ze[k]), __ldg(&e[k]), s);
            float t = P - 2.0f * s;
            float dv = t + __ldg(&g_c[col]);
            if (dv < bd || (dv == bd && col < bi)) { bd = dv; bi = col; }
        }
    }
    #pragma unroll
    for (int o = 16; o > 0; o >>= 1) {
        float od = __shfl_xor_sync(0xffffffffu, bd, o);
        int oi = __shfl_xor_sync(0xffffffffu, bi, o);
        if (od < bd || (od == bd && oi < bi)) { bd = od; bi = oi; }
    }
    if (lane == 0) {
        g_idx[row] = bi;
        if (write_idx) out_idx_f[row] = (float)bi;
    }
}

// ================= proven small kernels ======================================
__global__ void rowsumsq_kernel(const float* __restrict__ src, float* __restrict__ dst,
                                int rows, int cols)
{
    int row  = blockIdx.x * (blockDim.x >> 5) + (threadIdx.x >> 5);
    int lane = threadIdx.x & 31;
    if (row >= rows) return;
    const float* r = src + (size_t)row * cols;
    double s = 0.0;
    for (int j = lane; j < cols; j += 32) {
        float v = r[j];
        s += (double)v * (double)v;
    }
    #pragma unroll
    for (int o = 16; o > 0; o >>= 1) s += __shfl_down_sync(0xffffffffu, s, o);
    if (lane == 0) dst[row] = (float)s;
}

__global__ void loss_zq_kernel(const float* __restrict__ cb)
{
    int row = blockIdx.x;
    const float* ze = g_ze + (size_t)row * L_;
    const float* q  = cb   + (size_t)g_idx[row] * L_;
    float* zq = g_zq + (size_t)row * L_;
    double s = 0.0;
    for (int j = threadIdx.x; j < L_; j += blockDim.x) {
        float z = ze[j], qq = q[j];
        float dlt = qq - z;
        s += (double)dlt * (double)dlt;
        zq[j] = z + dlt;
    }
    __shared__ double sh[256];
    sh[threadIdx.x] = s;
    __syncthreads();
    for (int o = 128; o > 0; o >>= 1) {
        if (threadIdx.x < o) sh[threadIdx.x] += sh[threadIdx.x + o];
        __syncthreads();
    }
    if (threadIdx.x == 0) g_rowloss[row] = sh[0];
}

__global__ void loss_reduce_kernel(float* __restrict__ out_loss)
{
    __shared__ double sh[256];
    double s = 0.0;
    for (int r = threadIdx.x; r < B_; r += 256) s += g_rowloss[r];
    sh[threadIdx.x] = s;
    __syncthreads();
    for (int o = 128; o > 0; o >>= 1) {
        if (threadIdx.x < o) sh[threadIdx.x] += sh[threadIdx.x + o];
        __syncthreads();
    }
    if (threadIdx.x == 0) {
        float m = (float)(sh[0] / ((double)B_ * (double)L_));
        out_loss[0] = m + 0.25f * m;
    }
}

__global__ void softmax_kernel(float* __restrict__ logits)
{
    int row = blockIdx.x;
    float* p = logits + (size_t)row * O_;
    float v = p[threadIdx.x];
    __shared__ float shm[4];
    float m = v;
    #pragma unroll
    for (int o = 16; o > 0; o >>= 1) m = fmaxf(m, __shfl_xor_sync(0xffffffffu, m, o));
    if ((threadIdx.x & 31) == 0) shm[threadIdx.x >> 5] = m;
    __syncthreads();
    float mm = fmaxf(fmaxf(shm[0], shm[1]), fmaxf(shm[2], shm[3]));
    __syncthreads();
    float e = expf(v - mm);
    float s = e;
    #pragma unroll
    for (int o = 16; o > 0; o >>= 1) s += __shfl_xor_sync(0xffffffffu, s, o);
    if ((threadIdx.x & 31) == 0) shm[threadIdx.x >> 5] = s;
    __syncthreads();
    float ss = shm[0] + shm[1] + shm[2] + shm[3];
    p[threadIdx.x] = e / ss;
}

// ================= launch =====================================================
extern "C" void kernel_launch(void* const* d_in, const int* in_sizes, int n_in,
                              void* d_out, int out_size)
{
    const float* x     = (const float*)d_in[0];
    const float* W_enc = (const float*)d_in[1];
    const float* b_enc = (const float*)d_in[2];
    const float* cb    = (const float*)d_in[3];
    const float* W_cls = (const float*)d_in[4];
    const float* b_cls = (const float*)d_in[5];
    float* out = (float*)d_out;

    float* out_logits = out;
    float* out_loss   = out + (size_t)B_ * O_;
    float* out_idx    = out + (size_t)B_ * O_ + 1;
    int has_loss = (out_size >= B_ * O_ + 1);
    int has_idx  = (out_size >= B_ * O_ + 1 + B_);

    void *p;
    float *ze, *zq, *Pv, *cv;
    cudaGetSymbolAddress(&p, g_ze); ze = (float*)p;
    cudaGetSymbolAddress(&p, g_zq); zq = (float*)p;
    cudaGetSymbolAddress(&p, g_P);  Pv = (float*)p;
    cudaGetSymbolAddress(&p, g_c);  cv = (float*)p;

    // prep: codebook norms + scaled half2 codebook
    rowsumsq_kernel<<<K_ / 8, 256>>>(cb, cv, K_, L_);
    cbhalf_kernel<<<(unsigned)((size_t)K_ * LW2 / 256), 256>>>(cb);
    init_rowmax_kernel<<<B_ / 256, 256>>>();

    // z_e = x @ W_enc^T + b_enc  (BK=16 f32x2, fused half2 output)
    {
        dim3 grid(L_ / 128, B_ / 128);
        sgemm_x2_nt_bias<<<grid, 256>>>(x, W_enc, b_enc, ze, B_, L_, TD_, 1);
    }
    rowsumsq_kernel<<<B_ / 8, 256>>>(ze, Pv, B_, L_);

    // half2 HFMA2 dot GEMM (BK=16) + rowmax, then collect + exact refine
    {
        dim3 grid(K_ / 128, B_ / 128);
        dist_h2_kernel<<<grid, 256>>>();
    }
    scan_kernel<<<B_ / 8, 256>>>();
    refine_kernel<<<B_ / 8, 256>>>(cb, out_idx, has_idx);

    // loss + z_q (proven path)
    loss_zq_kernel<<<B_, 256>>>(cb);
    if (has_loss) loss_reduce_kernel<<<1, 256>>>(out_loss);

    // classifier + softmax
    {
        dim3 grid(O_ / 128, B_ / 128);
        sgemm_x2_nt_bias<<<grid, 256>>>(zq, W_cls, b_cls, out_logits, B_, O_, L_, 0);
    }
    softmax_kernel<<<B_, 128>>>(out_logits);
}